// round 9
// baseline (speedup 1.0000x reference)
#include <cuda_runtime.h>
#include <cuda_bf16.h>
#include <cstdint>

// ClusteringLayer: q = normalize_rows( 1 / (1 + max(|x|^2 + |c|^2 - 2 x.c, 0)) )
// N = in_sizes[0]/64 rows, F=64, K=256, ALPHA=1 -> exponent exactly -1.
//
// tf32 warp-MMA (m16n8k8), N-split warp mapping (warp = all 64 rows x 64 cols).
// Row layout: 72-float stride, second 32-col half at +36 ("half-offset") and
// k-permutation within 8-blocks; physical block base pb(k)=8k+4*(k>=4).
// -> fragment LDS.64 conflict-free, convert-phase LDS.128 reads conflict-free,
//    convert-phase STS.64 pair-stores only 2-way. Crossbar budget/tile ~1540cyc
//    < DRAM budget ~1920cyc. cp.async prefetch; FFMA+FMNMX+RCP epilogue with
//    cross-warp row-sum transpose; streaming (.cs) output stores.

#define F_DIM 64
#define K_DIM 256
#define M_TILE 64
#define A_STRIDE 72     // row stride in floats (data occupies [0,68) per row)
#define NTHREADS 128
#define GRID_CTAS 304   // 2 per SM on GB300 (152 SMs)

// smem floats: sC 256*72 + cSqP 256 + sA 64*72 + xSq 64 + stage 64*72 + rowSumT 256
#define SMEM_FLOATS (K_DIM*A_STRIDE + K_DIM + M_TILE*A_STRIDE + M_TILE + M_TILE*A_STRIDE + 256)
#define SMEM_BYTES  (SMEM_FLOATS * 4)

__device__ __forceinline__ float f2tf(float x) {
    unsigned u;
    asm("cvt.rna.tf32.f32 %0, %1;" : "=r"(u) : "f"(x));
    return __uint_as_float(u);
}

__device__ __forceinline__ float frcp(float x) {
    float r;
    asm("rcp.approx.f32 %0, %1;" : "=f"(r) : "f"(x));
    return r;
}

__device__ __forceinline__ void stcs2(float* p, float a, float b) {
    asm volatile("st.global.cs.v2.f32 [%0], {%1,%2};" :: "l"(p), "f"(a), "f"(b));
}

// physical float offset of 8-col block b within a row (half-offset layout)
__device__ __host__ __forceinline__ int pb(int b) { return 8 * b + (b >= 4 ? 4 : 0); }

__device__ __forceinline__ void prefetch_tile(const float* __restrict__ X,
                                              size_t rowBase, float* stage, int tid) {
    const char* base = (const char*)(X + rowBase * F_DIM);
    #pragma unroll
    for (int i = 0; i < 8; i++) {
        int chunk = tid + i * NTHREADS;          // 0..1023: 16B chunks of 64x64 tile
        int row = chunk >> 4, c16 = chunk & 15;
        int physF = c16 * 4 + (c16 >= 8 ? 4 : 0);      // half-offset layout
        unsigned dst = (unsigned)__cvta_generic_to_shared(stage + row * A_STRIDE + physF);
        const char* src = base + (size_t)row * (F_DIM * 4) + c16 * 16;
        asm volatile("cp.async.cg.shared.global [%0], [%1], 16;" :: "r"(dst), "l"(src));
    }
    asm volatile("cp.async.commit_group;");
}

__global__ __launch_bounds__(NTHREADS, 2)
void cluster_kernel(const float* __restrict__ X, const float* __restrict__ C,
                    float* __restrict__ Q, int nTiles) {
    extern __shared__ float sm[];
    float* sC      = sm;                            // [256][72] tf32 (perm+half-off)
    float* cSqP    = sC + K_DIM * A_STRIDE;         // [256] = 1 + |c|^2
    float* sA      = cSqP + K_DIM;                  // [64][72] tf32 (perm+half-off)
    float* xSq     = sA + M_TILE * A_STRIDE;        // [64]
    float* stage   = xSq + M_TILE;                  // [64][72] raw fp32 (half-off)
    float* rowSumT = stage + M_TILE * A_STRIDE;     // [64][4] per-warp row sums

    const int tid  = threadIdx.x;
    const int lane = tid & 31;
    const int warp = tid >> 5;                // 0..3, warp owns cols [64w,64w+64)
    const int g    = lane >> 2;               // 0..7 (fragment row group)
    const int t4   = lane & 3;                // 0..3 (fragment col group)

    // ---- Centroids once per CTA: tf32 permuted into smem + 1+|c|^2 ----
    for (int r = tid; r < K_DIM; r += NTHREADS) {
        const float4* src = (const float4*)(C + (size_t)r * F_DIM);
        float ss = 0.f;
        #pragma unroll
        for (int b = 0; b < 8; b++) {             // 8-col blocks
            float4 v = src[2 * b];                // cols 8b..8b+3   (kl 0..3)
            float4 w = src[2 * b + 1];            // cols 8b+4..8b+7 (kl 4..7)
            ss += v.x * v.x + v.y * v.y + v.z * v.z + v.w * v.w;
            ss += w.x * w.x + w.y * w.y + w.z * w.z + w.w * w.w;
            float2* dst = (float2*)(sC + r * A_STRIDE + pb(b));
            // pair permutation: (kl, kl+4) -> positions (2kl, 2kl+1)
            dst[0] = make_float2(f2tf(v.x), f2tf(w.x));
            dst[1] = make_float2(f2tf(v.y), f2tf(w.y));
            dst[2] = make_float2(f2tf(v.z), f2tf(w.z));
            dst[3] = make_float2(f2tf(v.w), f2tf(w.w));
        }
        cSqP[r] = 1.0f + ss;
    }

    int t = blockIdx.x;
    if (t < nTiles) prefetch_tile(X, (size_t)t * M_TILE, stage, tid);
    __syncthreads();   // covers centroid stores (and orders first prefetch issue)

    for (; t < nTiles; t += gridDim.x) {
        const size_t rowBase = (size_t)t * M_TILE;

        // ---- Wait for staged tile; also fences previous iter's epilogue ----
        asm volatile("cp.async.wait_group 0;");
        __syncthreads();

        // ---- Convert staging -> permuted tf32 sA + exact x_sq ----
        // thread (r = tid>>1, h = tid&1) handles blocks 4h..4h+3 of row r.
        {
            int r = tid >> 1, h = tid & 1;
            const float* srow = stage + r * A_STRIDE;
            float* drow = sA + r * A_STRIDE;
            float ss = 0.f;
            #pragma unroll
            for (int j = 0; j < 4; j++) {
                int b = 4 * h + j;
                int base = pb(b);
                float4 v = *(const float4*)(srow + base);
                float4 w = *(const float4*)(srow + base + 4);
                ss += v.x * v.x + v.y * v.y + v.z * v.z + v.w * v.w;
                ss += w.x * w.x + w.y * w.y + w.z * w.z + w.w * w.w;
                float2* dst = (float2*)(drow + base);
                dst[0] = make_float2(f2tf(v.x), f2tf(w.x));
                dst[1] = make_float2(f2tf(v.y), f2tf(w.y));
                dst[2] = make_float2(f2tf(v.z), f2tf(w.z));
                dst[3] = make_float2(f2tf(v.w), f2tf(w.w));
            }
            ss += __shfl_xor_sync(0xffffffffu, ss, 1);
            if (h == 0) xSq[r] = ss;
        }
        __syncthreads();

        // ---- Kick prefetch of next tile (overlaps with MMA below) ----
        {
            int tn = t + gridDim.x;
            if (tn < nTiles) prefetch_tile(X, (size_t)tn * M_TILE, stage, tid);
        }

        // ---- Cross-term GEMM: 64 rows x 64 cols per warp via m16n8k8 ----
        // acc[(m*8+nb)*4 + {0..3}]: rows {16m+g, 16m+8+g}, cols 64w+8nb+{2t4,2t4+1}
        float acc[128];
        #pragma unroll
        for (int i = 0; i < 128; i++) acc[i] = 0.f;

        #pragma unroll
        for (int k = 0; k < 8; k++) {
            const int k0 = pb(k) + 2 * t4;
            unsigned a0[4], a1[4], a2[4], a3[4];
            #pragma unroll
            for (int m = 0; m < 4; m++) {
                float2 lo = *(const float2*)(sA + (m * 16 + g) * A_STRIDE + k0);
                float2 hi = *(const float2*)(sA + (m * 16 + 8 + g) * A_STRIDE + k0);
                a0[m] = __float_as_uint(lo.x); a2[m] = __float_as_uint(lo.y);
                a1[m] = __float_as_uint(hi.x); a3[m] = __float_as_uint(hi.y);
            }
            #pragma unroll
            for (int nb = 0; nb < 8; nb++) {
                float2 b = *(const float2*)(sC + (warp * 64 + nb * 8 + g) * A_STRIDE + k0);
                unsigned b0 = __float_as_uint(b.x), b1 = __float_as_uint(b.y);
                #pragma unroll
                for (int m = 0; m < 4; m++) {
                    float* c = acc + (m * 8 + nb) * 4;
                    asm volatile(
                        "mma.sync.aligned.m16n8k8.row.col.f32.tf32.tf32.f32 "
                        "{%0,%1,%2,%3}, {%4,%5,%6,%7}, {%8,%9}, {%0,%1,%2,%3};"
                        : "+f"(c[0]), "+f"(c[1]), "+f"(c[2]), "+f"(c[3])
                        : "r"(a0[m]), "r"(a1[m]), "r"(a2[m]), "r"(a3[m]),
                          "r"(b0), "r"(b1));
                }
            }
        }

        // ---- Epilogue: q = 1/max(1 + x^2 + c^2 - 2xc, 1); partial row sums ----
        float rs0[4], rs1[4];
        #pragma unroll
        for (int m = 0; m < 4; m++) { rs0[m] = 0.f; rs1[m] = 0.f; }

        #pragma unroll
        for (int m = 0; m < 4; m++) {
            const float xs0 = xSq[m * 16 + g];
            const float xs1 = xSq[m * 16 + 8 + g];
            #pragma unroll
            for (int nb = 0; nb < 8; nb++) {
                float2 cs = *(const float2*)(cSqP + warp * 64 + nb * 8 + 2 * t4);
                float* c = acc + (m * 8 + nb) * 4;
                float q00 = frcp(fmaxf(fmaf(-2.f, c[0], xs0 + cs.x), 1.0f));
                float q01 = frcp(fmaxf(fmaf(-2.f, c[1], xs0 + cs.y), 1.0f));
                float q10 = frcp(fmaxf(fmaf(-2.f, c[2], xs1 + cs.x), 1.0f));
                float q11 = frcp(fmaxf(fmaf(-2.f, c[3], xs1 + cs.y), 1.0f));
                c[0] = q00; c[1] = q01; c[2] = q10; c[3] = q11;
                rs0[m] += q00 + q01;
                rs1[m] += q10 + q11;
            }
        }
        // reduce over the 4-lane column group, then publish per-warp row sums
        #pragma unroll
        for (int m = 0; m < 4; m++) {
            rs0[m] += __shfl_xor_sync(0xffffffffu, rs0[m], 1);
            rs0[m] += __shfl_xor_sync(0xffffffffu, rs0[m], 2);
            rs1[m] += __shfl_xor_sync(0xffffffffu, rs1[m], 1);
            rs1[m] += __shfl_xor_sync(0xffffffffu, rs1[m], 2);
        }
        if (t4 == 0) {
            #pragma unroll
            for (int m = 0; m < 4; m++) {
                rowSumT[(m * 16 + g) * 4 + warp]     = rs0[m];
                rowSumT[(m * 16 + 8 + g) * 4 + warp] = rs1[m];
            }
        }
        __syncthreads();

        // ---- Normalize with full row sums and store (cols go 2t4 within 8) ----
        #pragma unroll
        for (int m = 0; m < 4; m++) {
            float4 v0 = *(const float4*)(rowSumT + (m * 16 + g) * 4);
            float4 v1 = *(const float4*)(rowSumT + (m * 16 + 8 + g) * 4);
            const float inv0 = frcp((v0.x + v0.y) + (v0.z + v0.w));
            const float inv1 = frcp((v1.x + v1.y) + (v1.z + v1.w));
            const size_t orow0 = (rowBase + m * 16 + g) * (size_t)K_DIM + warp * 64;
            const size_t orow1 = orow0 + 8 * (size_t)K_DIM;
            #pragma unroll
            for (int nb = 0; nb < 8; nb++) {
                float* c = acc + (m * 8 + nb) * 4;
                stcs2(Q + orow0 + nb * 8 + 2 * t4, c[0] * inv0, c[1] * inv0);
                stcs2(Q + orow1 + nb * 8 + 2 * t4, c[2] * inv1, c[3] * inv1);
            }
        }
        // no trailing sync: top-of-loop wait_group + __syncthreads orders this
        // epilogue's xSq/rowSumT reads against the next iteration's writes.
    }
}

extern "C" void kernel_launch(void* const* d_in, const int* in_sizes, int n_in,
                              void* d_out, int out_size) {
    const float* X = (const float*)d_in[0];
    const float* C = (const float*)d_in[1];
    float* Q = (float*)d_out;

    const int N = in_sizes[0] / F_DIM;
    const int nTiles = N / M_TILE;

    cudaFuncSetAttribute(cluster_kernel,
                         cudaFuncAttributeMaxDynamicSharedMemorySize, SMEM_BYTES);

    int grid = nTiles < GRID_CTAS ? nTiles : GRID_CTAS;
    cluster_kernel<<<grid, NTHREADS, SMEM_BYTES>>>(X, C, Q, nTiles);
}

// round 17
// speedup vs baseline: 1.0536x; 1.0536x over previous
#include <cuda_runtime.h>
#include <cuda_bf16.h>
#include <cstdint>

// ClusteringLayer: q = normalize_rows( 1 / (1 + max(|x|^2 + |c|^2 - 2 x.c, 0)) )
// N = in_sizes[0]/64 rows, F=64, K=256, ALPHA=1 -> exponent exactly -1.
//
// R9 ncu: occ 12.3%, issue 47% -> latency-bound (regs=207 from acc[128]).
// This round: 256 threads / 8 warps per CTA, warp = 32 rows x 64 cols,
// acc[64] -> ~110 regs -> 16 warps/SM (2 CTAs). Same tf32 m16n8k8 path,
// half-offset + k-permuted smem layout (conflict-free frag LDS.64),
// cp.async prefetch, FFMA+FMNMX+RCP epilogue, streaming stores.

#define F_DIM 64
#define K_DIM 256
#define M_TILE 64
#define A_STRIDE 72     // row stride in floats (data occupies [0,68) per row)
#define NTHREADS 256
#define GRID_CTAS 304   // 2 per SM on GB300 (152 SMs)

// smem floats: sC 256*72 + cSqP 256 + sA 64*72 + xSq 64 + stage 64*72 + rowSumT 256
#define SMEM_FLOATS (K_DIM*A_STRIDE + K_DIM + M_TILE*A_STRIDE + M_TILE + M_TILE*A_STRIDE + 256)
#define SMEM_BYTES  (SMEM_FLOATS * 4)

__device__ __forceinline__ float f2tf(float x) {
    unsigned u;
    asm("cvt.rna.tf32.f32 %0, %1;" : "=r"(u) : "f"(x));
    return __uint_as_float(u);
}

__device__ __forceinline__ float frcp(float x) {
    float r;
    asm("rcp.approx.f32 %0, %1;" : "=f"(r) : "f"(x));
    return r;
}

__device__ __forceinline__ void stcs2(float* p, float a, float b) {
    asm volatile("st.global.cs.v2.f32 [%0], {%1,%2};" :: "l"(p), "f"(a), "f"(b));
}

// physical float offset of 8-col block b within a row (half-offset layout)
__device__ __host__ __forceinline__ int pb(int b) { return 8 * b + (b >= 4 ? 4 : 0); }

__device__ __forceinline__ void prefetch_tile(const float* __restrict__ X,
                                              size_t rowBase, float* stage, int tid) {
    const char* base = (const char*)(X + rowBase * F_DIM);
    #pragma unroll
    for (int i = 0; i < 4; i++) {
        int chunk = tid + i * NTHREADS;          // 0..1023: 16B chunks of 64x64 tile
        int row = chunk >> 4, c16 = chunk & 15;
        int physF = c16 * 4 + (c16 >= 8 ? 4 : 0);      // half-offset layout
        unsigned dst = (unsigned)__cvta_generic_to_shared(stage + row * A_STRIDE + physF);
        const char* src = base + (size_t)row * (F_DIM * 4) + c16 * 16;
        asm volatile("cp.async.cg.shared.global [%0], [%1], 16;" :: "r"(dst), "l"(src));
    }
    asm volatile("cp.async.commit_group;");
}

__global__ __launch_bounds__(NTHREADS, 2)
void cluster_kernel(const float* __restrict__ X, const float* __restrict__ C,
                    float* __restrict__ Q, int nTiles) {
    extern __shared__ float sm[];
    float* sC      = sm;                            // [256][72] tf32 (perm+half-off)
    float* cSqP    = sC + K_DIM * A_STRIDE;         // [256] = 1 + |c|^2
    float* sA      = cSqP + K_DIM;                  // [64][72] tf32 (perm+half-off)
    float* xSq     = sA + M_TILE * A_STRIDE;        // [64]
    float* stage   = xSq + M_TILE;                  // [64][72] raw fp32 (half-off)
    float* rowSumT = stage + M_TILE * A_STRIDE;     // [64][4] per-col-quad row sums

    const int tid  = threadIdx.x;
    const int lane = tid & 31;
    const int warp = tid >> 5;                // 0..7
    const int h    = warp >> 2;               // 0/1: row half (rows 32h..32h+31)
    const int wc   = warp & 3;                // 0..3: col quarter (cols 64wc..)
    const int g    = lane >> 2;               // 0..7 (fragment row group)
    const int t4   = lane & 3;                // 0..3 (fragment col group)

    // ---- Centroids once per CTA: tf32 permuted into smem + 1+|c|^2 ----
    for (int r = tid; r < K_DIM; r += NTHREADS) {
        const float4* src = (const float4*)(C + (size_t)r * F_DIM);
        float ss = 0.f;
        #pragma unroll
        for (int b = 0; b < 8; b++) {             // 8-col blocks
            float4 v = src[2 * b];                // cols 8b..8b+3   (kl 0..3)
            float4 w = src[2 * b + 1];            // cols 8b+4..8b+7 (kl 4..7)
            ss += v.x * v.x + v.y * v.y + v.z * v.z + v.w * v.w;
            ss += w.x * w.x + w.y * w.y + w.z * w.z + w.w * w.w;
            float2* dst = (float2*)(sC + r * A_STRIDE + pb(b));
            // pair permutation: (kl, kl+4) -> positions (2kl, 2kl+1)
            dst[0] = make_float2(f2tf(v.x), f2tf(w.x));
            dst[1] = make_float2(f2tf(v.y), f2tf(w.y));
            dst[2] = make_float2(f2tf(v.z), f2tf(w.z));
            dst[3] = make_float2(f2tf(v.w), f2tf(w.w));
        }
        cSqP[r] = 1.0f + ss;
    }

    int t = blockIdx.x;
    if (t < nTiles) prefetch_tile(X, (size_t)t * M_TILE, stage, tid);
    __syncthreads();   // covers centroid stores (and orders first prefetch issue)

    for (; t < nTiles; t += gridDim.x) {
        const size_t rowBase = (size_t)t * M_TILE;

        // ---- Wait for staged tile; also fences previous iter's epilogue ----
        asm volatile("cp.async.wait_group 0;");
        __syncthreads();

        // ---- Convert staging -> permuted tf32 sA + exact x_sq ----
        // thread (r = tid>>2, qq = tid&3) handles blocks 2qq, 2qq+1 of row r.
        {
            int r = tid >> 2, qq = tid & 3;
            const float* srow = stage + r * A_STRIDE;
            float* drow = sA + r * A_STRIDE;
            float ss = 0.f;
            #pragma unroll
            for (int j = 0; j < 2; j++) {
                int b = 2 * qq + j;
                int base = pb(b);
                float4 v = *(const float4*)(srow + base);
                float4 w = *(const float4*)(srow + base + 4);
                ss += v.x * v.x + v.y * v.y + v.z * v.z + v.w * v.w;
                ss += w.x * w.x + w.y * w.y + w.z * w.z + w.w * w.w;
                float2* dst = (float2*)(drow + base);
                dst[0] = make_float2(f2tf(v.x), f2tf(w.x));
                dst[1] = make_float2(f2tf(v.y), f2tf(w.y));
                dst[2] = make_float2(f2tf(v.z), f2tf(w.z));
                dst[3] = make_float2(f2tf(v.w), f2tf(w.w));
            }
            ss += __shfl_xor_sync(0xffffffffu, ss, 1);
            ss += __shfl_xor_sync(0xffffffffu, ss, 2);
            if (qq == 0) xSq[r] = ss;
        }
        __syncthreads();

        // ---- Kick prefetch of next tile (overlaps with MMA below) ----
        {
            int tn = t + gridDim.x;
            if (tn < nTiles) prefetch_tile(X, (size_t)tn * M_TILE, stage, tid);
        }

        // ---- Cross-term GEMM: 32 rows x 64 cols per warp via m16n8k8 ----
        // acc[(m*8+nb)*4+{0..3}]: rows {32h+16m+g, +8}, cols 64wc+8nb+{2t4,2t4+1}
        float acc[64];
        #pragma unroll
        for (int i = 0; i < 64; i++) acc[i] = 0.f;

        #pragma unroll
        for (int k = 0; k < 8; k++) {
            const int k0 = pb(k) + 2 * t4;
            unsigned a0[2], a1[2], a2[2], a3[2];
            #pragma unroll
            for (int m = 0; m < 2; m++) {
                float2 lo = *(const float2*)(sA + (h * 32 + m * 16 + g) * A_STRIDE + k0);
                float2 hi = *(const float2*)(sA + (h * 32 + m * 16 + 8 + g) * A_STRIDE + k0);
                a0[m] = __float_as_uint(lo.x); a2[m] = __float_as_uint(lo.y);
                a1[m] = __float_as_uint(hi.x); a3[m] = __float_as_uint(hi.y);
            }
            #pragma unroll
            for (int nb = 0; nb < 8; nb++) {
                float2 b = *(const float2*)(sC + (wc * 64 + nb * 8 + g) * A_STRIDE + k0);
                unsigned b0 = __float_as_uint(b.x), b1 = __float_as_uint(b.y);
                #pragma unroll
                for (int m = 0; m < 2; m++) {
                    float* c = acc + (m * 8 + nb) * 4;
                    asm volatile(
                        "mma.sync.aligned.m16n8k8.row.col.f32.tf32.tf32.f32 "
                        "{%0,%1,%2,%3}, {%4,%5,%6,%7}, {%8,%9}, {%0,%1,%2,%3};"
                        : "+f"(c[0]), "+f"(c[1]), "+f"(c[2]), "+f"(c[3])
                        : "r"(a0[m]), "r"(a1[m]), "r"(a2[m]), "r"(a3[m]),
                          "r"(b0), "r"(b1));
                }
            }
        }

        // ---- Epilogue: q = 1/max(1 + x^2 + c^2 - 2xc, 1); partial row sums ----
        float rs0[2], rs1[2];
        #pragma unroll
        for (int m = 0; m < 2; m++) { rs0[m] = 0.f; rs1[m] = 0.f; }

        #pragma unroll
        for (int m = 0; m < 2; m++) {
            const float xs0 = xSq[h * 32 + m * 16 + g];
            const float xs1 = xSq[h * 32 + m * 16 + 8 + g];
            #pragma unroll
            for (int nb = 0; nb < 8; nb++) {
                float2 cs = *(const float2*)(cSqP + wc * 64 + nb * 8 + 2 * t4);
                float* c = acc + (m * 8 + nb) * 4;
                float q00 = frcp(fmaxf(fmaf(-2.f, c[0], xs0 + cs.x), 1.0f));
                float q01 = frcp(fmaxf(fmaf(-2.f, c[1], xs0 + cs.y), 1.0f));
                float q10 = frcp(fmaxf(fmaf(-2.f, c[2], xs1 + cs.x), 1.0f));
                float q11 = frcp(fmaxf(fmaf(-2.f, c[3], xs1 + cs.y), 1.0f));
                c[0] = q00; c[1] = q01; c[2] = q10; c[3] = q11;
                rs0[m] += q00 + q01;
                rs1[m] += q10 + q11;
            }
        }
        // reduce over the 4-lane column group, publish per-col-quad row sums
        #pragma unroll
        for (int m = 0; m < 2; m++) {
            rs0[m] += __shfl_xor_sync(0xffffffffu, rs0[m], 1);
            rs0[m] += __shfl_xor_sync(0xffffffffu, rs0[m], 2);
            rs1[m] += __shfl_xor_sync(0xffffffffu, rs1[m], 1);
            rs1[m] += __shfl_xor_sync(0xffffffffu, rs1[m], 2);
        }
        if (t4 == 0) {
            #pragma unroll
            for (int m = 0; m < 2; m++) {
                rowSumT[(h * 32 + m * 16 + g) * 4 + wc]     = rs0[m];
                rowSumT[(h * 32 + m * 16 + 8 + g) * 4 + wc] = rs1[m];
            }
        }
        __syncthreads();

        // ---- Normalize with full row sums and store ----
        #pragma unroll
        for (int m = 0; m < 2; m++) {
            float4 v0 = *(const float4*)(rowSumT + (h * 32 + m * 16 + g) * 4);
            float4 v1 = *(const float4*)(rowSumT + (h * 32 + m * 16 + 8 + g) * 4);
            const float inv0 = frcp((v0.x + v0.y) + (v0.z + v0.w));
            const float inv1 = frcp((v1.x + v1.y) + (v1.z + v1.w));
            const size_t orow0 = (rowBase + h * 32 + m * 16 + g) * (size_t)K_DIM + wc * 64;
            const size_t orow1 = orow0 + 8 * (size_t)K_DIM;
            #pragma unroll
            for (int nb = 0; nb < 8; nb++) {
                float* c = acc + (m * 8 + nb) * 4;
                stcs2(Q + orow0 + nb * 8 + 2 * t4, c[0] * inv0, c[1] * inv0);
                stcs2(Q + orow1 + nb * 8 + 2 * t4, c[2] * inv1, c[3] * inv1);
            }
        }
        // no trailing sync: top-of-loop wait_group + __syncthreads orders this
        // epilogue's xSq/rowSumT reads against the next iteration's writes.
    }
}

extern "C" void kernel_launch(void* const* d_in, const int* in_sizes, int n_in,
                              void* d_out, int out_size) {
    const float* X = (const float*)d_in[0];
    const float* C = (const float*)d_in[1];
    float* Q = (float*)d_out;

    const int N = in_sizes[0] / F_DIM;
    const int nTiles = N / M_TILE;

    cudaFuncSetAttribute(cluster_kernel,
                         cudaFuncAttributeMaxDynamicSharedMemorySize, SMEM_BYTES);

    int grid = nTiles < GRID_CTAS ? nTiles : GRID_CTAS;
    cluster_kernel<<<grid, NTHREADS, SMEM_BYTES>>>(X, C, Q, nTiles);
}